// round 2
// baseline (speedup 1.0000x reference)
#include <cuda_runtime.h>
#include <cuda_fp16.h>
#include <cstdint>
#include <math.h>

#define NTOK 8192
#define HD   1024
#define ID   4096
#define NE   8

// ---------------- scratch (static device globals; no allocs) ----------------
__device__ __align__(256) __half g_W1h[(size_t)NE * HD * ID];   // 64 MB
__device__ __align__(256) __half g_Woh[(size_t)ID * HD];        // 8 MB
__device__ __align__(256) __half g_xh[(size_t)NTOK * HD];       // 16 MB (permuted fp16 activations)
__device__ __align__(256) __half g_inter[(size_t)NTOK * ID];    // 64 MB (permuted)
__device__ __align__(256) float  g_y[(size_t)NTOK * HD];        // 32 MB (permuted, +bo)
__device__ int g_expert[NTOK];
__device__ int g_perm[NTOK];
__device__ int g_counts[NE];
__device__ int g_offsets[NE + 1];
__device__ int g_cursor[NE];

// ---------------- small helpers ----------------
__device__ __forceinline__ void cpa16(void* s, const void* g) {
    uint32_t a = (uint32_t)__cvta_generic_to_shared(s);
    asm volatile("cp.async.cg.shared.global [%0], [%1], 16;" :: "r"(a), "l"(g));
}
__device__ __forceinline__ void ldsm4(uint32_t& r0, uint32_t& r1, uint32_t& r2, uint32_t& r3, const void* p) {
    uint32_t a = (uint32_t)__cvta_generic_to_shared(p);
    asm volatile("ldmatrix.sync.aligned.m8n8.x4.shared.b16 {%0,%1,%2,%3}, [%4];"
                 : "=r"(r0), "=r"(r1), "=r"(r2), "=r"(r3) : "r"(a));
}
__device__ __forceinline__ void ldsm4t(uint32_t& r0, uint32_t& r1, uint32_t& r2, uint32_t& r3, const void* p) {
    uint32_t a = (uint32_t)__cvta_generic_to_shared(p);
    asm volatile("ldmatrix.sync.aligned.m8n8.x4.trans.shared.b16 {%0,%1,%2,%3}, [%4];"
                 : "=r"(r0), "=r"(r1), "=r"(r2), "=r"(r3) : "r"(a));
}
__device__ __forceinline__ void mma16816(float c[4], const uint32_t a[4], const uint32_t b[2]) {
    asm volatile("mma.sync.aligned.m16n8k16.row.col.f32.f16.f16.f32 "
                 "{%0,%1,%2,%3}, {%4,%5,%6,%7}, {%8,%9}, {%0,%1,%2,%3};"
                 : "+f"(c[0]), "+f"(c[1]), "+f"(c[2]), "+f"(c[3])
                 : "r"(a[0]), "r"(a[1]), "r"(a[2]), "r"(a[3]), "r"(b[0]), "r"(b[1]));
}
__device__ __forceinline__ float gelu_exact(float v) {
    return 0.5f * v * (1.0f + erff(v * 0.70710678118654752f));
}

// ---------------- pipeline kernels ----------------
__global__ void init_kernel() {
    int t = threadIdx.x;
    if (t < NE) { g_counts[t] = 0; g_cursor[t] = 0; }
}

// fp32 -> fp16 weight conversion (once per launch)
__global__ void convert_kernel(const float4* __restrict__ W1, const float4* __restrict__ Wo) {
    size_t i = (size_t)blockIdx.x * blockDim.x + threadIdx.x;
    const size_t n1 = (size_t)NE * HD * ID / 4;
    const size_t n2 = (size_t)ID * HD / 4;
    if (i < n1) {
        float4 v = W1[i];
        __half2* d = (__half2*)g_W1h;
        d[2 * i]     = __floats2half2_rn(v.x, v.y);
        d[2 * i + 1] = __floats2half2_rn(v.z, v.w);
    } else if (i < n1 + n2) {
        size_t j = i - n1;
        float4 v = Wo[j];
        __half2* d = (__half2*)g_Woh;
        d[2 * j]     = __floats2half2_rn(v.x, v.y);
        d[2 * j + 1] = __floats2half2_rn(v.z, v.w);
    }
}

// router: fp32 logits + argmax (must be fp32-exact-ish so argmax matches ref)
__global__ void router_kernel(const float* __restrict__ x, const float* __restrict__ Wr) {
    __shared__ float4 Wrs[NE * 256];  // 32 KB
    int tid = threadIdx.x;
    const float4* Wr4 = (const float4*)Wr;
    for (int i = tid; i < NE * 256; i += 256) Wrs[i] = Wr4[i];
    __syncthreads();
    int warp = tid >> 5, lane = tid & 31;
    int n = blockIdx.x * 8 + warp;
    const float4* xr = (const float4*)(x + (size_t)n * HD);
    float acc[NE];
#pragma unroll
    for (int e = 0; e < NE; e++) acc[e] = 0.f;
#pragma unroll
    for (int j = 0; j < 8; j++) {
        float4 v = xr[j * 32 + lane];
#pragma unroll
        for (int e = 0; e < NE; e++) {
            float4 w = Wrs[e * 256 + j * 32 + lane];
            acc[e] += v.x * w.x + v.y * w.y + v.z * w.z + v.w * w.w;
        }
    }
#pragma unroll
    for (int e = 0; e < NE; e++)
#pragma unroll
        for (int o = 16; o > 0; o >>= 1) acc[e] += __shfl_xor_sync(0xffffffffu, acc[e], o);
    if (lane == 0) {
        int best = 0; float bv = acc[0];
#pragma unroll
        for (int e = 1; e < NE; e++) if (acc[e] > bv) { bv = acc[e]; best = e; }  // first-max tie-break == jnp.argmax
        g_expert[n] = best;
        atomicAdd(&g_counts[best], 1);
    }
}

__global__ void scan_kernel() {
    int off = 0;
    for (int e = 0; e < NE; e++) { g_offsets[e] = off; off += g_counts[e]; }
    g_offsets[NE] = off;
}

__global__ void scatter_kernel() {
    int t = blockIdx.x * 256 + threadIdx.x;
    if (t >= NTOK) return;
    int e = g_expert[t];
    int pos = g_offsets[e] + atomicAdd(&g_cursor[e], 1);
    g_perm[pos] = t;
}

// gather permuted rows and convert to fp16
__global__ void gather_kernel(const float* __restrict__ x) {
    int pos = blockIdx.x;
    int tok = g_perm[pos];
    const float4* src = (const float4*)(x + (size_t)tok * HD);
    __half2* dst = (__half2*)(g_xh + (size_t)pos * HD);
    for (int i = threadIdx.x; i < 256; i += 128) {
        float4 v = src[i];
        dst[2 * i]     = __floats2half2_rn(v.x, v.y);
        dst[2 * i + 1] = __floats2half2_rn(v.z, v.w);
    }
}

// ---------------- fp16 tensor-core GEMM core ----------------
// 128x128x64 CTA tile, 8 warps (4x2), warp tile 32x64, cp.async double buffer,
// XOR-swizzled smem (16B granule ^ (row&7)) -> conflict-free ldmatrix.
template <int EPI>
__device__ __forceinline__ void gemm_core(
    const __half* __restrict__ A, int lda,
    const __half* __restrict__ B, int ldb,
    const float* __restrict__ bias,
    int M, int K,
    __half* __restrict__ outH, float* __restrict__ outF, int ldc,
    int m0, int n0, char* smem)
{
    __half* As = (__half*)smem;               // [2][128*64]
    __half* Bs = (__half*)smem + 2 * 128 * 64;  // [2][64*128]
    const int tid = threadIdx.x;
    const int lane = tid & 31, wid = tid >> 5;
    const int wm = wid >> 1, wn = wid & 1;

    float acc[2][8][4];
#pragma unroll
    for (int i = 0; i < 2; i++)
#pragma unroll
        for (int j = 0; j < 8; j++)
#pragma unroll
            for (int k = 0; k < 4; k++) acc[i][j][k] = 0.f;

    const int nk = K >> 6;

    auto load_tile = [&](int kt, int buf) {
        const int k0 = kt << 6;
        __half* as = As + buf * (128 * 64);
        __half* bs = Bs + buf * (64 * 128);
#pragma unroll
        for (int i = 0; i < 4; i++) {               // A: 128 rows x 8 granules
            int c = tid + i * 256;
            int r = c >> 3, g = c & 7;
            int gr = m0 + r; if (gr >= M) gr = M - 1;   // clamp tail rows (never stored)
            cpa16(as + r * 64 + ((g ^ (r & 7)) << 3), A + (size_t)gr * lda + k0 + (g << 3));
        }
#pragma unroll
        for (int i = 0; i < 4; i++) {               // B: 64 rows x 16 granules
            int c = tid + i * 256;
            int r = c >> 4, g = c & 15;
            cpa16(bs + r * 128 + ((g ^ (r & 7)) << 3), B + (size_t)(k0 + r) * ldb + n0 + (g << 3));
        }
        asm volatile("cp.async.commit_group;");
    };

    load_tile(0, 0);
    for (int kt = 0; kt < nk; kt++) {
        int buf = kt & 1;
        if (kt + 1 < nk) {
            load_tile(kt + 1, buf ^ 1);
            asm volatile("cp.async.wait_group 1;");
        } else {
            asm volatile("cp.async.wait_group 0;");
        }
        __syncthreads();
        __half* as = As + buf * (128 * 64);
        __half* bs = Bs + buf * (64 * 128);
#pragma unroll
        for (int ks = 0; ks < 4; ks++) {
            const int kk = ks << 4;
            uint32_t af[2][4];
#pragma unroll
            for (int mi = 0; mi < 2; mi++) {
                int mr = wm * 32 + mi * 16 + (lane & 15);
                int kc = kk + ((lane >> 4) << 3);
                int g = kc >> 3;
                ldsm4(af[mi][0], af[mi][1], af[mi][2], af[mi][3],
                      as + mr * 64 + ((g ^ (mr & 7)) << 3));
            }
            uint32_t bf[8][2];
#pragma unroll
            for (int nj = 0; nj < 4; nj++) {
                int kr = kk + (lane & 15);
                int nc = wn * 64 + nj * 16 + ((lane >> 4) << 3);
                int g = nc >> 3;
                ldsm4t(bf[2 * nj][0], bf[2 * nj][1], bf[2 * nj + 1][0], bf[2 * nj + 1][1],
                       bs + kr * 128 + ((g ^ (kr & 7)) << 3));
            }
#pragma unroll
            for (int mi = 0; mi < 2; mi++)
#pragma unroll
                for (int ni = 0; ni < 8; ni++)
                    mma16816(acc[mi][ni], af[mi], bf[ni]);
        }
        __syncthreads();
    }

    // epilogue: c0:(g,2t) c1:(g,2t+1) c2:(g+8,2t) c3:(g+8,2t+1)
    const int gq = lane >> 2, tq = lane & 3;
#pragma unroll
    for (int mi = 0; mi < 2; mi++) {
#pragma unroll
        for (int rr = 0; rr < 2; rr++) {
            int lr = wm * 32 + mi * 16 + gq + rr * 8;
            int grow = m0 + lr;
            if (grow < M) {
#pragma unroll
                for (int ni = 0; ni < 8; ni++) {
                    int col = n0 + wn * 64 + ni * 8 + tq * 2;
                    float v0 = acc[mi][ni][rr * 2 + 0] + bias[col];
                    float v1 = acc[mi][ni][rr * 2 + 1] + bias[col + 1];
                    if (EPI == 1) {
                        v0 = gelu_exact(v0);
                        v1 = gelu_exact(v1);
                        *(__half2*)(outH + (size_t)grow * ldc + col) = __floats2half2_rn(v0, v1);
                    } else {
                        float2 f; f.x = v0; f.y = v1;
                        *(float2*)(outF + (size_t)grow * ldc + col) = f;
                    }
                }
            }
        }
    }
}

// grouped GEMM1: inter = gelu(xh @ W1[e] + b1[e]), per-expert contiguous rows
__global__ __launch_bounds__(256, 2) void gemm1_kernel(const float* __restrict__ b1) {
    extern __shared__ char smem[];
    int e = blockIdx.z;
    int off = g_offsets[e];
    int Me = g_offsets[e + 1] - off;
    int m0 = blockIdx.y << 7;
    if (m0 >= Me) return;
    int n0 = blockIdx.x << 7;
    gemm_core<1>(g_xh + (size_t)off * HD, HD,
                 g_W1h + (size_t)e * HD * ID, ID,
                 b1 + (size_t)e * ID, Me, HD,
                 g_inter + (size_t)off * ID, nullptr, ID, m0, n0, smem);
}

// dense GEMM2: y = inter @ Wo + bo (all tokens, shared weights)
__global__ __launch_bounds__(256, 2) void gemm2_kernel(const float* __restrict__ bo) {
    extern __shared__ char smem[];
    gemm_core<2>(g_inter, ID, g_Woh, HD, bo, NTOK, ID,
                 nullptr, g_y, HD, blockIdx.y << 7, blockIdx.x << 7, smem);
}

// LayerNorm epilogue with exact fp32 residual + un-permute
__global__ void ln_kernel(const float* __restrict__ x, const float* __restrict__ gamma,
                          const float* __restrict__ beta, float* __restrict__ out) {
    int pos = blockIdx.x;
    int tok = g_perm[pos];
    const float* yr = g_y + (size_t)pos * HD;
    const float* xr = x + (size_t)tok * HD;
    int tid = threadIdx.x;
    float v[4]; float s = 0.f, s2 = 0.f;
#pragma unroll
    for (int j = 0; j < 4; j++) {
        int i = tid + j * 256;
        v[j] = yr[i] + xr[i];
        s += v[j]; s2 += v[j] * v[j];
    }
    __shared__ float red[64];
#pragma unroll
    for (int o = 16; o > 0; o >>= 1) {
        s  += __shfl_xor_sync(0xffffffffu, s, o);
        s2 += __shfl_xor_sync(0xffffffffu, s2, o);
    }
    int w = tid >> 5;
    if ((tid & 31) == 0) { red[w] = s; red[32 + w] = s2; }
    __syncthreads();
    if (tid < 32) {
        float a = (tid < 8) ? red[tid] : 0.f;
        float b = (tid < 8) ? red[32 + tid] : 0.f;
#pragma unroll
        for (int o = 4; o > 0; o >>= 1) {
            a += __shfl_xor_sync(0xffffffffu, a, o);
            b += __shfl_xor_sync(0xffffffffu, b, o);
        }
        if (tid == 0) { red[0] = a; red[32] = b; }
    }
    __syncthreads();
    float mu = red[0] * (1.0f / HD);
    float var = red[32] * (1.0f / HD) - mu * mu;
    float rs = rsqrtf(var + 1e-12f);
    float* orow = out + (size_t)tok * HD;
#pragma unroll
    for (int j = 0; j < 4; j++) {
        int i = tid + j * 256;
        orow[i] = (v[j] - mu) * rs * gamma[i] + beta[i];
    }
}

// ---------------- launch ----------------
extern "C" void kernel_launch(void* const* d_in, const int* in_sizes, int n_in,
                              void* d_out, int out_size) {
    const float* x     = (const float*)d_in[0];
    const float* Wr    = (const float*)d_in[1];
    const float* W1    = (const float*)d_in[2];
    const float* b1    = (const float*)d_in[3];
    const float* Wo    = (const float*)d_in[4];
    const float* bo    = (const float*)d_in[5];
    const float* gamma = (const float*)d_in[6];
    const float* beta  = (const float*)d_in[7];
    float* out = (float*)d_out;
    (void)in_sizes; (void)n_in; (void)out_size;

    cudaFuncSetAttribute(gemm1_kernel, cudaFuncAttributeMaxDynamicSharedMemorySize, 65536);
    cudaFuncSetAttribute(gemm2_kernel, cudaFuncAttributeMaxDynamicSharedMemorySize, 65536);

    init_kernel<<<1, 32>>>();
    convert_kernel<<<36864, 256>>>((const float4*)W1, (const float4*)Wo);
    router_kernel<<<1024, 256>>>(x, Wr);
    scan_kernel<<<1, 1>>>();
    scatter_kernel<<<32, 256>>>();
    gather_kernel<<<8192, 128>>>(x);

    dim3 g1(ID / 128, NTOK / 128, NE);   // 32 x 64 x 8 (empty row-tiles early-exit)
    gemm1_kernel<<<g1, 256, 65536>>>(b1);

    dim3 g2(HD / 128, NTOK / 128, 1);    // 8 x 64
    gemm2_kernel<<<g2, 256, 65536>>>(bo);

    ln_kernel<<<8192, 256>>>(x, gamma, beta, out);
}